// round 9
// baseline (speedup 1.0000x reference)
#include <cuda_runtime.h>
#include <cuda_bf16.h>
#include <math.h>
#include <stdint.h>

#define EPS   1e-5f
#define NTHR  512

// ---- SMEM layout (bytes) ----
#define XS_OFF   0                          // xs: [16 pairs][512 thr] float2 = 64KB
#define AP_OFF   65536                      // Apack: 128*68*8 = 69632
#define WB0_OFF  135168                     // 16KB
#define WB1_OFF  151552                     // 16KB
#define PRM_OFF  167936                     // 13 vec * 1KB
#define PS_OFF   181248                     // 4*64*4 = 1KB
#define PSQ_OFF  182272                     // 1KB
#define SMEM_TOTAL 183296

// prepped weights: [gemm][ktile][4096 u32]; u32 i: u4=i>>2, comp=i&3,
// ntg=u4>>5, lane=u4&31, sel=comp>>1 (hi/lo), which=comp&1 (k+0/k+8)
__device__ __align__(16) uint32_t g_wpack[4][16][4096];

__device__ __forceinline__ uint32_t s2u(const void* p) {
    uint32_t a;
    asm("{ .reg .u64 t; cvta.to.shared.u64 t, %1; cvt.u32.u64 %0, t; }" : "=r"(a) : "l"(p));
    return a;
}

__device__ __forceinline__ void hmma(float* c, const uint32_t* a, uint32_t b0, uint32_t b1) {
    asm volatile("mma.sync.aligned.m16n8k16.row.col.f32.bf16.bf16.f32 "
        "{%0,%1,%2,%3}, {%4,%5,%6,%7}, {%8,%9}, {%0,%1,%2,%3};"
        : "+f"(c[0]), "+f"(c[1]), "+f"(c[2]), "+f"(c[3])
        : "r"(a[0]), "r"(a[1]), "r"(a[2]), "r"(a[3]), "r"(b0), "r"(b1));
}

__device__ __forceinline__ void cp16(uint32_t dst, const void* src) {
    uint64_t gp = __cvta_generic_to_global(src);
    asm volatile("cp.async.cg.shared.global [%0], [%1], 16;" :: "r"(dst), "l"(gp));
}
#define CP_COMMIT() asm volatile("cp.async.commit_group;" ::: "memory")
#define CP_WAIT0()  asm volatile("cp.async.wait_group 0;" ::: "memory")

// cvt-pipe split (R7 version — R8's PRMT variant overloaded the ALU pipe)
__device__ __forceinline__ void split2(float v0, float v1, uint32_t& hi, uint32_t& lo) {
    __nv_bfloat162 h = __floats2bfloat162_rn(v0, v1);
    float r0 = v0 - __bfloat162float(h.x);
    float r1 = v1 - __bfloat162float(h.y);
    __nv_bfloat162 l = __floats2bfloat162_rn(r0, r1);
    hi = *reinterpret_cast<uint32_t*>(&h);
    lo = *reinterpret_cast<uint32_t*>(&l);
}

__device__ __forceinline__ float gelu(float x) {
    return 0.5f * x * (1.0f + erff(x * 0.70710678118654752f));
}

// ---- prep: pack W (fp32 [k][n]) -> fragment-ready uint4 {bh0,bh1,bl0,bl1} per lane ----
__global__ void prep_w(const float* __restrict__ W11, const float* __restrict__ W12,
                       const float* __restrict__ W21, const float* __restrict__ W22) {
    const float* Ws[4] = {W11, W12, W21, W22};
    int gi = blockIdx.x >> 4, kt = blockIdx.x & 15;
    const float* W = Ws[gi];
    for (int i = threadIdx.x; i < 4096; i += blockDim.x) {
        int comp = i & 3, u4 = i >> 2;
        int lane = u4 & 31, ntg = u4 >> 5;
        int sel = comp >> 1, which = comp & 1;
        int t = lane & 3, gg = lane >> 2;
        int n = ntg * 8 + gg;
        int k = kt * 16 + t * 2 + (which ? 8 : 0);
        float w0 = W[k * 256 + n], w1 = W[(k + 1) * 256 + n];
        __nv_bfloat16 h0 = __float2bfloat16(w0), h1 = __float2bfloat16(w1);
        __nv_bfloat162 r;
        if (sel == 0) { r.x = h0; r.y = h1; }
        else {
            r.x = __float2bfloat16(w0 - __bfloat162float(h0));
            r.y = __float2bfloat16(w1 - __bfloat162float(h1));
        }
        g_wpack[gi][kt][i] = *reinterpret_cast<uint32_t*>(&r);
    }
}

// chunk-0 prefetch (into WB0) — overlaps preceding epilogue
__device__ __forceinline__ void prefetch_c0(uint32_t sb, const uint32_t* wsrc, int tid) {
    uint32_t d = sb + WB0_OFF + tid * 16;
    const char* s = (const char*)wsrc + tid * 16;
    cp16(d, s);
    cp16(d + 8192, s + 8192);
    CP_COMMIT();
}

// ---- one fused 64x256x256 GEMM (3-term split); chunk0 already in flight ----
__device__ __forceinline__ void gemm256(char* smem, uint32_t sb, const uint32_t* wsrc,
                                        float (&c)[8][4], int tid, int wn,
                                        int m0g, int m0g8, int t) {
    const uint2* ap = (const uint2*)(smem + AP_OFF);
#pragma unroll
    for (int nt = 0; nt < 8; nt++)
#pragma unroll
        for (int q = 0; q < 4; q++) c[nt][q] = 0.f;

    const uint32_t dst0 = sb + WB0_OFF + tid * 16;
    const uint32_t dst1 = sb + WB1_OFF + tid * 16;
    const char* src = (const char*)wsrc + tid * 16;
    const int wboff = wn * 4096 + (tid & 31) * 16;

    for (int kt = 0; kt < 16; kt++) {
        CP_WAIT0();
        __syncthreads();
        if (kt + 1 < 16) {
            uint32_t d = ((kt + 1) & 1) ? dst1 : dst0;
            const char* s = src + (kt + 1) * 16384;
            cp16(d, s);
            cp16(d + 8192, s + 8192);
            CP_COMMIT();
        }
        int k2 = kt * 8 + t;
        uint2 p0 = ap[k2 * 68 + m0g];
        uint2 p1 = ap[k2 * 68 + m0g8];
        uint2 p2 = ap[(k2 + 4) * 68 + m0g];
        uint2 p3 = ap[(k2 + 4) * 68 + m0g8];
        uint32_t ahi[4] = {p0.x, p1.x, p2.x, p3.x};
        uint32_t alo[4] = {p0.y, p1.y, p2.y, p3.y};
        const char* wb = smem + ((kt & 1) ? WB1_OFF : WB0_OFF) + wboff;
#pragma unroll
        for (int nt = 0; nt < 8; nt++) {
            uint4 b = *(const uint4*)(wb + nt * 512);
            hmma(c[nt], ahi, b.x, b.y);
            hmma(c[nt], alo, b.x, b.y);
            hmma(c[nt], ahi, b.z, b.w);
        }
    }
}

__device__ __forceinline__ void ln_stats(float (&c)[8][4], float* psum, float* psq,
                                         int wn, int m0g, int m0g8, int t,
                                         float& mu0, float& rs0, float& mu1, float& rs1) {
    float s0 = 0, q0 = 0, s1 = 0, q1 = 0;
#pragma unroll
    for (int nt = 0; nt < 8; nt++) {
        s0 += c[nt][0] + c[nt][1]; q0 += c[nt][0] * c[nt][0] + c[nt][1] * c[nt][1];
        s1 += c[nt][2] + c[nt][3]; q1 += c[nt][2] * c[nt][2] + c[nt][3] * c[nt][3];
    }
    s0 += __shfl_xor_sync(~0u, s0, 1); s0 += __shfl_xor_sync(~0u, s0, 2);
    q0 += __shfl_xor_sync(~0u, q0, 1); q0 += __shfl_xor_sync(~0u, q0, 2);
    s1 += __shfl_xor_sync(~0u, s1, 1); s1 += __shfl_xor_sync(~0u, s1, 2);
    q1 += __shfl_xor_sync(~0u, q1, 1); q1 += __shfl_xor_sync(~0u, q1, 2);
    if (t == 0) {
        psum[wn * 64 + m0g] = s0;  psq[wn * 64 + m0g] = q0;
        psum[wn * 64 + m0g8] = s1; psq[wn * 64 + m0g8] = q1;
    }
    __syncthreads();
    float ts0 = psum[m0g] + psum[64 + m0g] + psum[128 + m0g] + psum[192 + m0g];
    float tq0 = psq[m0g] + psq[64 + m0g] + psq[128 + m0g] + psq[192 + m0g];
    float ts1 = psum[m0g8] + psum[64 + m0g8] + psum[128 + m0g8] + psum[192 + m0g8];
    float tq1 = psq[m0g8] + psq[64 + m0g8] + psq[128 + m0g8] + psq[192 + m0g8];
    mu0 = ts0 * (1.f / 256.f); rs0 = rsqrtf(tq0 * (1.f / 256.f) - mu0 * mu0 + EPS);
    mu1 = ts1 * (1.f / 256.f); rs1 = rsqrtf(tq1 * (1.f / 256.f) - mu1 * mu1 + EPS);
}

__device__ __forceinline__ void norm_split(float (&c)[8][4], const float* gv, const float* bv,
                                           float mu0, float rs0, float mu1, float rs1,
                                           uint2* ap, int wn, int t, int m0g, int m0g8) {
#pragma unroll
    for (int nt = 0; nt < 8; nt++) {
        int cg = wn * 64 + nt * 8 + t * 2;
        float2 gg = *(const float2*)(gv + cg);
        float2 bb = *(const float2*)(bv + cg);
        float v0 = (c[nt][0] - mu0) * rs0 * gg.x + bb.x;
        float v1 = (c[nt][1] - mu0) * rs0 * gg.y + bb.y;
        float v2 = (c[nt][2] - mu1) * rs1 * gg.x + bb.x;
        float v3 = (c[nt][3] - mu1) * rs1 * gg.y + bb.y;
        uint32_t h01, l01, h23, l23;
        split2(v0, v1, h01, l01);
        split2(v2, v3, h23, l23);
        int k2 = wn * 32 + nt * 4 + t;
        ap[k2 * 68 + m0g]  = make_uint2(h01, l01);
        ap[k2 * 68 + m0g8] = make_uint2(h23, l23);
    }
}

__device__ __forceinline__ void gelu_split(float (&c)[8][4], const float* bv,
                                           uint2* ap, int wn, int t, int m0g, int m0g8) {
    __syncthreads();   // all warps out of previous GEMM before Apack overwrite
#pragma unroll
    for (int nt = 0; nt < 8; nt++) {
        int cg = wn * 64 + nt * 8 + t * 2;
        float2 bb = *(const float2*)(bv + cg);
        float v0 = gelu(c[nt][0] + bb.x);
        float v1 = gelu(c[nt][1] + bb.y);
        float v2 = gelu(c[nt][2] + bb.x);
        float v3 = gelu(c[nt][3] + bb.y);
        uint32_t h01, l01, h23, l23;
        split2(v0, v1, h01, l01);
        split2(v2, v3, h23, l23);
        int k2 = wn * 32 + nt * 4 + t;
        ap[k2 * 68 + m0g]  = make_uint2(h01, l01);
        ap[k2 * 68 + m0g8] = make_uint2(h23, l23);
    }
}

__global__ void __launch_bounds__(NTHR, 1)
stab_hmma(const float* __restrict__ meas, const float* __restrict__ event,
          const float* __restrict__ leak, const float* __restrict__ event_leak,
          const int* __restrict__ stab_ids, const int* __restrict__ cycle_ids,
          const float* __restrict__ w_meas, const float* __restrict__ b_meas,
          const float* __restrict__ w_event, const float* __restrict__ b_event,
          const float* __restrict__ w_leak, const float* __restrict__ b_leak,
          const float* __restrict__ w_el, const float* __restrict__ b_el,
          const float* __restrict__ stab_table, const float* __restrict__ cycle_table,
          const float* __restrict__ g1, const float* __restrict__ be1,
          const float* __restrict__ b11, const float* __restrict__ b12,
          const float* __restrict__ g2, const float* __restrict__ be2,
          const float* __restrict__ b21, const float* __restrict__ b22,
          float* __restrict__ out) {
    extern __shared__ char smem[];
    const uint32_t sb = s2u(smem);
    float*  prm  = (float*)(smem + PRM_OFF);
    float*  psum = (float*)(smem + PS_OFF);
    float*  psq  = (float*)(smem + PSQ_OFF);
    float2* xsp  = (float2*)(smem + XS_OFF);
    uint2*  ap   = (uint2*)(smem + AP_OFF);

    const int tid = threadIdx.x, w = tid >> 5, lane = tid & 31;
    const int wm = w & 3, wn = w >> 2, t = lane & 3, g = lane >> 2;
    const int m0g = wm * 16 + g, m0g8 = m0g + 8;
    const int base = blockIdx.x * 64;
    const int r0 = base + m0g, r1 = base + m0g8;

    {   // stage params: slot0=bcomb, 1..12 below
        const float* P[12] = {w_meas, w_event, w_leak, w_el, g1, be1, b11, b12, g2, be2, b21, b22};
        for (int i = tid; i < 12 * 256; i += NTHR) prm[256 + i] = P[i >> 8][i & 255];
        for (int i = tid; i < 256; i += NTHR)
            prm[i] = b_meas[i] + b_event[i] + b_leak[i] + b_el[i];
    }
    __syncthreads();

    float c[8][4];

    // ---- embed (values land directly in C/A-fragment layout) ----
    {
        float me0 = meas[r0], me1 = meas[r1];
        float ev0 = event[r0], ev1 = event[r1];
        float lk0 = leak[r0], lk1 = leak[r1];
        float el0 = event_leak[r0], el1 = event_leak[r1];
        const float* st0 = stab_table + (size_t)stab_ids[r0] * 256;
        const float* st1 = stab_table + (size_t)stab_ids[r1] * 256;
        const float* cy0 = cycle_table + (size_t)cycle_ids[r0] * 256;
        const float* cy1 = cycle_table + (size_t)cycle_ids[r1] * 256;
#pragma unroll
        for (int nt = 0; nt < 8; nt++) {
            int cg = wn * 64 + nt * 8 + t * 2;
            float2 bc  = *(const float2*)(prm + 0 * 256 + cg);
            float2 wmv = *(const float2*)(prm + 1 * 256 + cg);
            float2 wev = *(const float2*)(prm + 2 * 256 + cg);
            float2 wlv = *(const float2*)(prm + 3 * 256 + cg);
            float2 wzv = *(const float2*)(prm + 4 * 256 + cg);
            float2 s0 = *(const float2*)(st0 + cg), s1 = *(const float2*)(st1 + cg);
            float2 q0 = *(const float2*)(cy0 + cg), q1 = *(const float2*)(cy1 + cg);
            c[nt][0] = bc.x + me0 * wmv.x + ev0 * wev.x + lk0 * wlv.x + el0 * wzv.x + s0.x + q0.x;
            c[nt][1] = bc.y + me0 * wmv.y + ev0 * wev.y + lk0 * wlv.y + el0 * wzv.y + s0.y + q0.y;
            c[nt][2] = bc.x + me1 * wmv.x + ev1 * wev.x + lk1 * wlv.x + el1 * wzv.x + s1.x + q1.x;
            c[nt][3] = bc.y + me1 * wmv.y + ev1 * wev.y + lk1 * wlv.y + el1 * wzv.y + s1.y + q1.y;
            xsp[(nt * 2 + 0) * NTHR + tid] = make_float2(c[nt][0], c[nt][1]);
            xsp[(nt * 2 + 1) * NTHR + tid] = make_float2(c[nt][2], c[nt][3]);
        }
    }

    // prefetch GEMM1 chunk0 under the LN1 epilogue
    prefetch_c0(sb, &g_wpack[0][0][0], tid);

    float mu0, rs0, mu1, rs1;
    ln_stats(c, psum, psq, wn, m0g, m0g8, t, mu0, rs0, mu1, rs1);
    norm_split(c, prm + 5 * 256, prm + 6 * 256, mu0, rs0, mu1, rs1, ap, wn, t, m0g, m0g8);

    // GEMM1 ; GELU(+b11)
    gemm256(smem, sb, &g_wpack[0][0][0], c, tid, wn, m0g, m0g8, t);
    prefetch_c0(sb, &g_wpack[1][0][0], tid);
    gelu_split(c, prm + 7 * 256, ap, wn, t, m0g, m0g8);

    // GEMM2 ; x += D + b12 ; LN2
    gemm256(smem, sb, &g_wpack[1][0][0], c, tid, wn, m0g, m0g8, t);
    prefetch_c0(sb, &g_wpack[2][0][0], tid);
#pragma unroll
    for (int nt = 0; nt < 8; nt++) {
        int cg = wn * 64 + nt * 8 + t * 2;
        float2 bb = *(const float2*)(prm + 8 * 256 + cg);
        float2 x0 = xsp[(nt * 2 + 0) * NTHR + tid];
        float2 x1 = xsp[(nt * 2 + 1) * NTHR + tid];
        c[nt][0] = x0.x + c[nt][0] + bb.x;
        c[nt][1] = x0.y + c[nt][1] + bb.y;
        c[nt][2] = x1.x + c[nt][2] + bb.x;
        c[nt][3] = x1.y + c[nt][3] + bb.y;
        xsp[(nt * 2 + 0) * NTHR + tid] = make_float2(c[nt][0], c[nt][1]);
        xsp[(nt * 2 + 1) * NTHR + tid] = make_float2(c[nt][2], c[nt][3]);
    }
    ln_stats(c, psum, psq, wn, m0g, m0g8, t, mu0, rs0, mu1, rs1);
    norm_split(c, prm + 9 * 256, prm + 10 * 256, mu0, rs0, mu1, rs1, ap, wn, t, m0g, m0g8);

    // GEMM3 ; GELU(+b21)
    gemm256(smem, sb, &g_wpack[2][0][0], c, tid, wn, m0g, m0g8, t);
    prefetch_c0(sb, &g_wpack[3][0][0], tid);
    gelu_split(c, prm + 11 * 256, ap, wn, t, m0g, m0g8);

    // GEMM4 ; out = x + D + b22
    gemm256(smem, sb, &g_wpack[3][0][0], c, tid, wn, m0g, m0g8, t);
#pragma unroll
    for (int nt = 0; nt < 8; nt++) {
        int cg = wn * 64 + nt * 8 + t * 2;
        float2 bb = *(const float2*)(prm + 12 * 256 + cg);
        float2 x0 = xsp[(nt * 2 + 0) * NTHR + tid];
        float2 x1 = xsp[(nt * 2 + 1) * NTHR + tid];
        *(float2*)(out + (size_t)r0 * 256 + cg) =
            make_float2(x0.x + c[nt][0] + bb.x, x0.y + c[nt][1] + bb.y);
        *(float2*)(out + (size_t)r1 * 256 + cg) =
            make_float2(x1.x + c[nt][2] + bb.x, x1.y + c[nt][3] + bb.y);
    }
}

extern "C" void kernel_launch(void* const* d_in, const int* in_sizes, int n_in,
                              void* d_out, int out_size) {
    const float* meas       = (const float*)d_in[0];
    const float* event      = (const float*)d_in[1];
    const float* leak       = (const float*)d_in[2];
    const float* event_leak = (const float*)d_in[3];
    const int*   stab_ids   = (const int*)d_in[4];
    const int*   cycle_ids  = (const int*)d_in[5];
    const float* w_meas  = (const float*)d_in[6];
    const float* b_meas  = (const float*)d_in[7];
    const float* w_event = (const float*)d_in[8];
    const float* b_event = (const float*)d_in[9];
    const float* w_leak  = (const float*)d_in[10];
    const float* b_leak  = (const float*)d_in[11];
    const float* w_el    = (const float*)d_in[12];
    const float* b_el    = (const float*)d_in[13];
    const float* stab_table  = (const float*)d_in[14];
    const float* cycle_table = (const float*)d_in[15];
    const float* g1  = (const float*)d_in[16];
    const float* be1 = (const float*)d_in[17];
    const float* W11 = (const float*)d_in[18];
    const float* b11 = (const float*)d_in[19];
    const float* W12 = (const float*)d_in[20];
    const float* b12 = (const float*)d_in[21];
    const float* g2  = (const float*)d_in[22];
    const float* be2 = (const float*)d_in[23];
    const float* W21 = (const float*)d_in[24];
    const float* b21 = (const float*)d_in[25];
    const float* W22 = (const float*)d_in[26];
    const float* b22 = (const float*)d_in[27];

    const int n_tokens = in_sizes[0];
    const int nblocks  = n_tokens / 64;    // 4096

    prep_w<<<64, 128>>>(W11, W12, W21, W22);

    cudaFuncSetAttribute(stab_hmma,
                         cudaFuncAttributeMaxDynamicSharedMemorySize, SMEM_TOTAL);
    stab_hmma<<<nblocks, NTHR, SMEM_TOTAL>>>(
        meas, event, leak, event_leak, stab_ids, cycle_ids,
        w_meas, b_meas, w_event, b_event, w_leak, b_leak, w_el, b_el,
        stab_table, cycle_table,
        g1, be1, b11, b12, g2, be2, b21, b22,
        (float*)d_out);
}

// round 10
// speedup vs baseline: 1.3143x; 1.3143x over previous
#include <cuda_runtime.h>
#include <cuda_fp16.h>
#include <math.h>
#include <stdint.h>

#define EPS   1e-5f
#define NTHR  256

// ---- SMEM layout (bytes) ----
#define XS_OFF   0                          // xs: [32 pairs][256 thr] float2 = 64KB
#define AP_OFF   65536                      // Apack: 128*68*8 = 69632
#define WB0_OFF  135168                     // 16KB chunk buf (2 kt)
#define WB1_OFF  151552                     // 16KB chunk buf
#define PRM_OFF  167936                     // 13 vec * 1KB
#define PS_OFF   181248
#define PSQ_OFF  181760
#define SMEM_TOTAL 182272

// prepped fp16 weights: [gemm][chunk 8][4096 u32]; chunk = 2 kt (16KB)
// within chunk: [kt_local 2][ntp 16][lane 32][comp 4]
//   comp: {nt=2ntp b0, nt=2ntp b1, nt=2ntp+1 b0, nt=2ntp+1 b1}
__device__ __align__(16) uint32_t g_wpack[4][8][4096];

__device__ __forceinline__ uint32_t s2u(const void* p) {
    uint32_t a;
    asm("{ .reg .u64 t; cvta.to.shared.u64 t, %1; cvt.u32.u64 %0, t; }" : "=r"(a) : "l"(p));
    return a;
}

__device__ __forceinline__ void hmma(float* c, const uint32_t* a, uint32_t b0, uint32_t b1) {
    asm volatile("mma.sync.aligned.m16n8k16.row.col.f32.f16.f16.f32 "
        "{%0,%1,%2,%3}, {%4,%5,%6,%7}, {%8,%9}, {%0,%1,%2,%3};"
        : "+f"(c[0]), "+f"(c[1]), "+f"(c[2]), "+f"(c[3])
        : "r"(a[0]), "r"(a[1]), "r"(a[2]), "r"(a[3]), "r"(b0), "r"(b1));
}

__device__ __forceinline__ void cp16(uint32_t dst, const void* src) {
    uint64_t gp = __cvta_generic_to_global(src);
    asm volatile("cp.async.cg.shared.global [%0], [%1], 16;" :: "r"(dst), "l"(gp));
}
#define CP_COMMIT() asm volatile("cp.async.commit_group;" ::: "memory")
#define CP_WAIT0()  asm volatile("cp.async.wait_group 0;" ::: "memory")

// 2-term fp16 split of activations (cvt pipe)
__device__ __forceinline__ void split2(float v0, float v1, uint32_t& hi, uint32_t& lo) {
    __half2 h = __floats2half2_rn(v0, v1);
    float r0 = v0 - __half2float(__low2half(h));
    float r1 = v1 - __half2float(__high2half(h));
    __half2 l = __floats2half2_rn(r0, r1);
    hi = *reinterpret_cast<uint32_t*>(&h);
    lo = *reinterpret_cast<uint32_t*>(&l);
}

__device__ __forceinline__ float gelu(float x) {
    return 0.5f * x * (1.0f + erff(x * 0.70710678118654752f));
}

// ---- prep: pack W (fp32 [k][n]) -> fragment-ready single-fp16 chunks ----
__global__ void prep_w(const float* __restrict__ W11, const float* __restrict__ W12,
                       const float* __restrict__ W21, const float* __restrict__ W22) {
    const float* Ws[4] = {W11, W12, W21, W22};
    int gi = blockIdx.x >> 3, cc = blockIdx.x & 7;
    const float* W = Ws[gi];
    for (int i = threadIdx.x; i < 4096; i += blockDim.x) {
        int kt_local = i >> 11;
        int j = i & 2047;
        int ntp = j >> 7;
        int lane = (j >> 2) & 31;
        int comp = j & 3;
        int nt = ntp * 2 + (comp >> 1);
        int which = comp & 1;
        int t = lane & 3, gg = lane >> 2;
        int n = nt * 8 + gg;
        int k = (cc * 2 + kt_local) * 16 + t * 2 + which * 8;
        __half2 r = __floats2half2_rn(W[k * 256 + n], W[(k + 1) * 256 + n]);
        g_wpack[gi][cc][i] = *reinterpret_cast<uint32_t*>(&r);
    }
}

// chunk-0 prefetch (into WB0) — overlaps preceding epilogue
__device__ __forceinline__ void prefetch_c0(uint32_t sb, const uint32_t* wsrc, int tid) {
    uint32_t d = sb + WB0_OFF + tid * 16;
    const char* s = (const char*)wsrc + tid * 16;
#pragma unroll
    for (int i = 0; i < 4; i++) cp16(d + i * 4096, s + i * 4096);
    CP_COMMIT();
}

// ---- one fused 64x256x256 GEMM (2-term fp16); chunk0 already in flight ----
__device__ __forceinline__ void gemm256(char* smem, uint32_t sb, const uint32_t* wsrc,
                                        float (&c)[16][4], int tid, int wn,
                                        int m0g, int m0g8, int t) {
    const uint2* ap = (const uint2*)(smem + AP_OFF);
#pragma unroll
    for (int nt = 0; nt < 16; nt++)
#pragma unroll
        for (int q = 0; q < 4; q++) c[nt][q] = 0.f;

    const uint32_t dst0 = sb + WB0_OFF + tid * 16;
    const uint32_t dst1 = sb + WB1_OFF + tid * 16;
    const char* src = (const char*)wsrc + tid * 16;
    const int wboff = wn * 4096 + (tid & 31) * 16;

    for (int ch = 0; ch < 8; ch++) {
        CP_WAIT0();
        __syncthreads();
        if (ch + 1 < 8) {
            uint32_t d = ((ch + 1) & 1) ? dst1 : dst0;
            const char* s = src + (ch + 1) * 16384;
#pragma unroll
            for (int i = 0; i < 4; i++) cp16(d + i * 4096, s + i * 4096);
            CP_COMMIT();
        }
        const char* cb = smem + ((ch & 1) ? WB1_OFF : WB0_OFF);
#pragma unroll
        for (int kl = 0; kl < 2; kl++) {
            int k2 = (ch * 2 + kl) * 8 + t;
            uint2 p0 = ap[k2 * 68 + m0g];
            uint2 p1 = ap[k2 * 68 + m0g8];
            uint2 p2 = ap[(k2 + 4) * 68 + m0g];
            uint2 p3 = ap[(k2 + 4) * 68 + m0g8];
            uint32_t ahi[4] = {p0.x, p1.x, p2.x, p3.x};
            uint32_t alo[4] = {p0.y, p1.y, p2.y, p3.y};
            const char* wb = cb + kl * 8192 + wboff;
#pragma unroll
            for (int jj = 0; jj < 8; jj++) {
                uint4 b = *(const uint4*)(wb + jj * 512);
                hmma(c[jj * 2],     ahi, b.x, b.y);
                hmma(c[jj * 2],     alo, b.x, b.y);
                hmma(c[jj * 2 + 1], ahi, b.z, b.w);
                hmma(c[jj * 2 + 1], alo, b.z, b.w);
            }
        }
    }
}

__device__ __forceinline__ void ln_stats(float (&c)[16][4], float* psum, float* psq,
                                         int wn, int m0g, int m0g8, int t,
                                         float& mu0, float& rs0, float& mu1, float& rs1) {
    float s0 = 0, q0 = 0, s1 = 0, q1 = 0;
#pragma unroll
    for (int nt = 0; nt < 16; nt++) {
        s0 += c[nt][0] + c[nt][1]; q0 += c[nt][0] * c[nt][0] + c[nt][1] * c[nt][1];
        s1 += c[nt][2] + c[nt][3]; q1 += c[nt][2] * c[nt][2] + c[nt][3] * c[nt][3];
    }
    s0 += __shfl_xor_sync(~0u, s0, 1); s0 += __shfl_xor_sync(~0u, s0, 2);
    q0 += __shfl_xor_sync(~0u, q0, 1); q0 += __shfl_xor_sync(~0u, q0, 2);
    s1 += __shfl_xor_sync(~0u, s1, 1); s1 += __shfl_xor_sync(~0u, s1, 2);
    q1 += __shfl_xor_sync(~0u, q1, 1); q1 += __shfl_xor_sync(~0u, q1, 2);
    if (t == 0) {
        psum[wn * 64 + m0g] = s0;  psq[wn * 64 + m0g] = q0;
        psum[wn * 64 + m0g8] = s1; psq[wn * 64 + m0g8] = q1;
    }
    __syncthreads();
    float ts0 = psum[m0g] + psum[64 + m0g],  tq0 = psq[m0g] + psq[64 + m0g];
    float ts1 = psum[m0g8] + psum[64 + m0g8], tq1 = psq[m0g8] + psq[64 + m0g8];
    mu0 = ts0 * (1.f / 256.f); rs0 = rsqrtf(tq0 * (1.f / 256.f) - mu0 * mu0 + EPS);
    mu1 = ts1 * (1.f / 256.f); rs1 = rsqrtf(tq1 * (1.f / 256.f) - mu1 * mu1 + EPS);
}

__device__ __forceinline__ void norm_split(float (&c)[16][4], const float* gv, const float* bv,
                                           float mu0, float rs0, float mu1, float rs1,
                                           uint2* ap, int wn, int t, int m0g, int m0g8) {
#pragma unroll
    for (int nt = 0; nt < 16; nt++) {
        int cg = wn * 128 + nt * 8 + t * 2;
        float2 gg = *(const float2*)(gv + cg);
        float2 bb = *(const float2*)(bv + cg);
        float v0 = (c[nt][0] - mu0) * rs0 * gg.x + bb.x;
        float v1 = (c[nt][1] - mu0) * rs0 * gg.y + bb.y;
        float v2 = (c[nt][2] - mu1) * rs1 * gg.x + bb.x;
        float v3 = (c[nt][3] - mu1) * rs1 * gg.y + bb.y;
        uint32_t h01, l01, h23, l23;
        split2(v0, v1, h01, l01);
        split2(v2, v3, h23, l23);
        int k2 = (wn * 16 + nt) * 4 + t;
        ap[k2 * 68 + m0g]  = make_uint2(h01, l01);
        ap[k2 * 68 + m0g8] = make_uint2(h23, l23);
    }
}

__device__ __forceinline__ void gelu_split(float (&c)[16][4], const float* bv,
                                           uint2* ap, int wn, int t, int m0g, int m0g8) {
    __syncthreads();   // all warps out of previous GEMM before Apack overwrite
#pragma unroll
    for (int nt = 0; nt < 16; nt++) {
        int cg = wn * 128 + nt * 8 + t * 2;
        float2 bb = *(const float2*)(bv + cg);
        float v0 = gelu(c[nt][0] + bb.x);
        float v1 = gelu(c[nt][1] + bb.y);
        float v2 = gelu(c[nt][2] + bb.x);
        float v3 = gelu(c[nt][3] + bb.y);
        uint32_t h01, l01, h23, l23;
        split2(v0, v1, h01, l01);
        split2(v2, v3, h23, l23);
        int k2 = (wn * 16 + nt) * 4 + t;
        ap[k2 * 68 + m0g]  = make_uint2(h01, l01);
        ap[k2 * 68 + m0g8] = make_uint2(h23, l23);
    }
}

__global__ void __launch_bounds__(NTHR, 1)
stab_hmma(const float* __restrict__ meas, const float* __restrict__ event,
          const float* __restrict__ leak, const float* __restrict__ event_leak,
          const int* __restrict__ stab_ids, const int* __restrict__ cycle_ids,
          const float* __restrict__ w_meas, const float* __restrict__ b_meas,
          const float* __restrict__ w_event, const float* __restrict__ b_event,
          const float* __restrict__ w_leak, const float* __restrict__ b_leak,
          const float* __restrict__ w_el, const float* __restrict__ b_el,
          const float* __restrict__ stab_table, const float* __restrict__ cycle_table,
          const float* __restrict__ g1, const float* __restrict__ be1,
          const float* __restrict__ b11, const float* __restrict__ b12,
          const float* __restrict__ g2, const float* __restrict__ be2,
          const float* __restrict__ b21, const float* __restrict__ b22,
          float* __restrict__ out) {
    extern __shared__ char smem[];
    const uint32_t sb = s2u(smem);
    float*  prm  = (float*)(smem + PRM_OFF);
    float*  psum = (float*)(smem + PS_OFF);
    float*  psq  = (float*)(smem + PSQ_OFF);
    float2* xsp  = (float2*)(smem + XS_OFF);
    uint2*  ap   = (uint2*)(smem + AP_OFF);

    const int tid = threadIdx.x, w = tid >> 5, lane = tid & 31;
    const int wm = w & 3, wn = w >> 2, t = lane & 3, g = lane >> 2;
    const int m0g = wm * 16 + g, m0g8 = m0g + 8;
    const int base = blockIdx.x * 64;
    const int r0 = base + m0g, r1 = base + m0g8;

    {   // stage params: slot0=bcomb, 1..12 below
        const float* P[12] = {w_meas, w_event, w_leak, w_el, g1, be1, b11, b12, g2, be2, b21, b22};
        for (int i = tid; i < 12 * 256; i += NTHR) prm[256 + i] = P[i >> 8][i & 255];
        for (int i = tid; i < 256; i += NTHR)
            prm[i] = b_meas[i] + b_event[i] + b_leak[i] + b_el[i];
    }
    __syncthreads();

    float c[16][4];

    // ---- embed (values land directly in C/A-fragment layout) ----
    {
        float me0 = meas[r0], me1 = meas[r1];
        float ev0 = event[r0], ev1 = event[r1];
        float lk0 = leak[r0], lk1 = leak[r1];
        float el0 = event_leak[r0], el1 = event_leak[r1];
        const float* st0 = stab_table + (size_t)stab_ids[r0] * 256;
        const float* st1 = stab_table + (size_t)stab_ids[r1] * 256;
        const float* cy0 = cycle_table + (size_t)cycle_ids[r0] * 256;
        const float* cy1 = cycle_table + (size_t)cycle_ids[r1] * 256;
#pragma unroll
        for (int nt = 0; nt < 16; nt++) {
            int cg = wn * 128 + nt * 8 + t * 2;
            float2 bc  = *(const float2*)(prm + 0 * 256 + cg);
            float2 wmv = *(const float2*)(prm + 1 * 256 + cg);
            float2 wev = *(const float2*)(prm + 2 * 256 + cg);
            float2 wlv = *(const float2*)(prm + 3 * 256 + cg);
            float2 wzv = *(const float2*)(prm + 4 * 256 + cg);
            float2 s0 = *(const float2*)(st0 + cg), s1 = *(const float2*)(st1 + cg);
            float2 q0 = *(const float2*)(cy0 + cg), q1 = *(const float2*)(cy1 + cg);
            c[nt][0] = bc.x + me0 * wmv.x + ev0 * wev.x + lk0 * wlv.x + el0 * wzv.x + s0.x + q0.x;
            c[nt][1] = bc.y + me0 * wmv.y + ev0 * wev.y + lk0 * wlv.y + el0 * wzv.y + s0.y + q0.y;
            c[nt][2] = bc.x + me1 * wmv.x + ev1 * wev.x + lk1 * wlv.x + el1 * wzv.x + s1.x + q1.x;
            c[nt][3] = bc.y + me1 * wmv.y + ev1 * wev.y + lk1 * wlv.y + el1 * wzv.y + s1.y + q1.y;
            xsp[(nt * 2 + 0) * 256 + tid] = make_float2(c[nt][0], c[nt][1]);
            xsp[(nt * 2 + 1) * 256 + tid] = make_float2(c[nt][2], c[nt][3]);
        }
    }

    // prefetch GEMM1 chunk0 under the LN1 epilogue
    prefetch_c0(sb, &g_wpack[0][0][0], tid);

    float mu0, rs0, mu1, rs1;
    ln_stats(c, psum, psq, wn, m0g, m0g8, t, mu0, rs0, mu1, rs1);
    norm_split(c, prm + 5 * 256, prm + 6 * 256, mu0, rs0, mu1, rs1, ap, wn, t, m0g, m0g8);

    // GEMM1 ; GELU(+b11)
    gemm256(smem, sb, &g_wpack[0][0][0], c, tid, wn, m0g, m0g8, t);
    prefetch_c0(sb, &g_wpack[1][0][0], tid);
    gelu_split(c, prm + 7 * 256, ap, wn, t, m0g, m0g8);

    // GEMM2 ; x += D + b12 ; LN2
    gemm256(smem, sb, &g_wpack[1][0][0], c, tid, wn, m0g, m0g8, t);
    prefetch_c0(sb, &g_wpack[2][0][0], tid);
#pragma unroll
    for (int nt = 0; nt < 16; nt++) {
        int cg = wn * 128 + nt * 8 + t * 2;
        float2 bb = *(const float2*)(prm + 8 * 256 + cg);
        float2 x0 = xsp[(nt * 2 + 0) * 256 + tid];
        float2 x1 = xsp[(nt * 2 + 1) * 256 + tid];
        c[nt][0] = x0.x + c[nt][0] + bb.x;
        c[nt][1] = x0.y + c[nt][1] + bb.y;
        c[nt][2] = x1.x + c[nt][2] + bb.x;
        c[nt][3] = x1.y + c[nt][3] + bb.y;
        xsp[(nt * 2 + 0) * 256 + tid] = make_float2(c[nt][0], c[nt][1]);
        xsp[(nt * 2 + 1) * 256 + tid] = make_float2(c[nt][2], c[nt][3]);
    }
    ln_stats(c, psum, psq, wn, m0g, m0g8, t, mu0, rs0, mu1, rs1);
    norm_split(c, prm + 9 * 256, prm + 10 * 256, mu0, rs0, mu1, rs1, ap, wn, t, m0g, m0g8);

    // GEMM3 ; GELU(+b21)
    gemm256(smem, sb, &g_wpack[2][0][0], c, tid, wn, m0g, m0g8, t);
    prefetch_c0(sb, &g_wpack[3][0][0], tid);
    gelu_split(c, prm + 11 * 256, ap, wn, t, m0g, m0g8);

    // GEMM4 ; out = x + D + b22
    gemm256(smem, sb, &g_wpack[3][0][0], c, tid, wn, m0g, m0g8, t);
#pragma unroll
    for (int nt = 0; nt < 16; nt++) {
        int cg = wn * 128 + nt * 8 + t * 2;
        float2 bb = *(const float2*)(prm + 12 * 256 + cg);
        float2 x0 = xsp[(nt * 2 + 0) * 256 + tid];
        float2 x1 = xsp[(nt * 2 + 1) * 256 + tid];
        *(float2*)(out + (size_t)r0 * 256 + cg) =
            make_float2(x0.x + c[nt][0] + bb.x, x0.y + c[nt][1] + bb.y);
        *(float2*)(out + (size_t)r1 * 256 + cg) =
            make_float2(x1.x + c[nt][2] + bb.x, x1.y + c[nt][3] + bb.y);
    }
}

extern "C" void kernel_launch(void* const* d_in, const int* in_sizes, int n_in,
                              void* d_out, int out_size) {
    const float* meas       = (const float*)d_in[0];
    const float* event      = (const float*)d_in[1];
    const float* leak       = (const float*)d_in[2];
    const float* event_leak = (const float*)d_in[3];
    const int*   stab_ids   = (const int*)d_in[4];
    const int*   cycle_ids  = (const int*)d_in[5];
    const float* w_meas  = (const float*)d_in[6];
    const float* b_meas  = (const float*)d_in[7];
    const float* w_event = (const float*)d_in[8];
    const float* b_event = (const float*)d_in[9];
    const float* w_leak  = (const float*)d_in[10];
    const float* b_leak  = (const float*)d_in[11];
    const float* w_el    = (const float*)d_in[12];
    const float* b_el    = (const float*)d_in[13];
    const float* stab_table  = (const float*)d_in[14];
    const float* cycle_table = (const float*)d_in[15];
    const float* g1  = (const float*)d_in[16];
    const float* be1 = (const float*)d_in[17];
    const float* W11 = (const float*)d_in[18];
    const float* b11 = (const float*)d_in[19];
    const float* W12 = (const float*)d_in[20];
    const float* b12 = (const float*)d_in[21];
    const float* g2  = (const float*)d_in[22];
    const float* be2 = (const float*)d_in[23];
    const float* W21 = (const float*)d_in[24];
    const float* b21 = (const float*)d_in[25];
    const float* W22 = (const float*)d_in[26];
    const float* b22 = (const float*)d_in[27];

    const int n_tokens = in_sizes[0];
    const int nblocks  = n_tokens / 64;    // 4096

    prep_w<<<32, 256>>>(W11, W12, W21, W22);

    cudaFuncSetAttribute(stab_hmma,
                         cudaFuncAttributeMaxDynamicSharedMemorySize, SMEM_TOTAL);
    stab_hmma<<<nblocks, NTHR, SMEM_TOTAL>>>(
        meas, event, leak, event_leak, stab_ids, cycle_ids,
        w_meas, b_meas, w_event, b_event, w_leak, b_leak, w_el, b_el,
        stab_table, cycle_table,
        g1, be1, b11, b12, g2, be2, b21, b22,
        (float*)d_out);
}

// round 11
// speedup vs baseline: 1.4355x; 1.0922x over previous
#include <cuda_runtime.h>
#include <cuda_fp16.h>
#include <math.h>
#include <stdint.h>

#define EPS   1e-5f
#define NTHR  256

// ---- SMEM layout (bytes) ----
#define AP_OFF   0                          // Apack: 128*68*8 = 69632 (embed params staged here first)
#define WB0_OFF  69632                      // 16KB chunk buf
#define WB1_OFF  86016                      // 16KB chunk buf
#define PRM_OFF  102400                     // 8 vec * 1KB
#define PS_OFF   110592                     // 512B
#define PSQ_OFF  111104                     // 512B
#define SMEM_TOTAL 111616                   // 109KB -> 2 CTAs/SM

// prepped fp16 weights: [gemm][chunk 8][4096 u32]; chunk = 2 kt (16KB)
__device__ __align__(16) uint32_t g_wpack[4][8][4096];

__device__ __forceinline__ uint32_t s2u(const void* p) {
    uint32_t a;
    asm("{ .reg .u64 t; cvta.to.shared.u64 t, %1; cvt.u32.u64 %0, t; }" : "=r"(a) : "l"(p));
    return a;
}

__device__ __forceinline__ void hmma(float* c, const uint32_t* a, uint32_t b0, uint32_t b1) {
    asm volatile("mma.sync.aligned.m16n8k16.row.col.f32.f16.f16.f32 "
        "{%0,%1,%2,%3}, {%4,%5,%6,%7}, {%8,%9}, {%0,%1,%2,%3};"
        : "+f"(c[0]), "+f"(c[1]), "+f"(c[2]), "+f"(c[3])
        : "r"(a[0]), "r"(a[1]), "r"(a[2]), "r"(a[3]), "r"(b0), "r"(b1));
}

__device__ __forceinline__ void cp16(uint32_t dst, const void* src) {
    uint64_t gp = __cvta_generic_to_global(src);
    asm volatile("cp.async.cg.shared.global [%0], [%1], 16;" :: "r"(dst), "l"(gp));
}
#define CP_COMMIT() asm volatile("cp.async.commit_group;" ::: "memory")
#define CP_WAIT0()  asm volatile("cp.async.wait_group 0;" ::: "memory")

// 2-term fp16 split of activations
__device__ __forceinline__ void split2(float v0, float v1, uint32_t& hi, uint32_t& lo) {
    __half2 h = __floats2half2_rn(v0, v1);
    float r0 = v0 - __half2float(__low2half(h));
    float r1 = v1 - __half2float(__high2half(h));
    __half2 l = __floats2half2_rn(r0, r1);
    hi = *reinterpret_cast<uint32_t*>(&h);
    lo = *reinterpret_cast<uint32_t*>(&l);
}

__device__ __forceinline__ float gelu(float x) {
    return 0.5f * x * (1.0f + erff(x * 0.70710678118654752f));
}

// ---- prep: pack W (fp32 [k][n]) -> fragment-ready single-fp16 chunks ----
__global__ void prep_w(const float* __restrict__ W11, const float* __restrict__ W12,
                       const float* __restrict__ W21, const float* __restrict__ W22) {
    const float* Ws[4] = {W11, W12, W21, W22};
    int gi = blockIdx.x >> 3, cc = blockIdx.x & 7;
    const float* W = Ws[gi];
    for (int i = threadIdx.x; i < 4096; i += blockDim.x) {
        int kt_local = i >> 11;
        int j = i & 2047;
        int ntp = j >> 7;
        int lane = (j >> 2) & 31;
        int comp = j & 3;
        int nt = ntp * 2 + (comp >> 1);
        int which = comp & 1;
        int t = lane & 3, gg = lane >> 2;
        int n = nt * 8 + gg;
        int k = (cc * 2 + kt_local) * 16 + t * 2 + which * 8;
        __half2 r = __floats2half2_rn(W[k * 256 + n], W[(k + 1) * 256 + n]);
        g_wpack[gi][cc][i] = *reinterpret_cast<uint32_t*>(&r);
    }
}

// chunk-0 prefetch (into WB0) — overlaps preceding epilogue
__device__ __forceinline__ void prefetch_c0(uint32_t sb, const uint32_t* wsrc, int tid) {
    uint32_t d = sb + WB0_OFF + tid * 16;
    const char* s = (const char*)wsrc + tid * 16;
#pragma unroll
    for (int i = 0; i < 4; i++) cp16(d + i * 4096, s + i * 4096);
    CP_COMMIT();
}

// ---- one fused 64x256x256 GEMM (2-term fp16); chunk0 already in flight ----
__device__ __forceinline__ void gemm256(char* smem, uint32_t sb, const uint32_t* wsrc,
                                        float (&c)[16][4], int tid, int wn,
                                        int m0g, int m0g8, int t) {
    const uint2* ap = (const uint2*)(smem + AP_OFF);
#pragma unroll
    for (int nt = 0; nt < 16; nt++)
#pragma unroll
        for (int q = 0; q < 4; q++) c[nt][q] = 0.f;

    const uint32_t dst0 = sb + WB0_OFF + tid * 16;
    const uint32_t dst1 = sb + WB1_OFF + tid * 16;
    const char* src = (const char*)wsrc + tid * 16;
    const int wboff = wn * 4096 + (tid & 31) * 16;

    for (int ch = 0; ch < 8; ch++) {
        CP_WAIT0();
        __syncthreads();
        if (ch + 1 < 8) {
            uint32_t d = ((ch + 1) & 1) ? dst1 : dst0;
            const char* s = src + (ch + 1) * 16384;
#pragma unroll
            for (int i = 0; i < 4; i++) cp16(d + i * 4096, s + i * 4096);
            CP_COMMIT();
        }
        const char* cb = smem + ((ch & 1) ? WB1_OFF : WB0_OFF);
#pragma unroll
        for (int kl = 0; kl < 2; kl++) {
            int k2 = (ch * 2 + kl) * 8 + t;
            uint2 p0 = ap[k2 * 68 + m0g];
            uint2 p1 = ap[k2 * 68 + m0g8];
            uint2 p2 = ap[(k2 + 4) * 68 + m0g];
            uint2 p3 = ap[(k2 + 4) * 68 + m0g8];
            uint32_t ahi[4] = {p0.x, p1.x, p2.x, p3.x};
            uint32_t alo[4] = {p0.y, p1.y, p2.y, p3.y};
            const char* wb = cb + kl * 8192 + wboff;
#pragma unroll
            for (int jj = 0; jj < 8; jj++) {
                uint4 b = *(const uint4*)(wb + jj * 512);
                hmma(c[jj * 2],     ahi, b.x, b.y);
                hmma(c[jj * 2],     alo, b.x, b.y);
                hmma(c[jj * 2 + 1], ahi, b.z, b.w);
                hmma(c[jj * 2 + 1], alo, b.z, b.w);
            }
        }
    }
}

__device__ __forceinline__ void ln_stats(float (&c)[16][4], float* psum, float* psq,
                                         int wn, int m0g, int m0g8, int t,
                                         float& mu0, float& rs0, float& mu1, float& rs1) {
    float s0 = 0, q0 = 0, s1 = 0, q1 = 0;
#pragma unroll
    for (int nt = 0; nt < 16; nt++) {
        s0 += c[nt][0] + c[nt][1]; q0 += c[nt][0] * c[nt][0] + c[nt][1] * c[nt][1];
        s1 += c[nt][2] + c[nt][3]; q1 += c[nt][2] * c[nt][2] + c[nt][3] * c[nt][3];
    }
    s0 += __shfl_xor_sync(~0u, s0, 1); s0 += __shfl_xor_sync(~0u, s0, 2);
    q0 += __shfl_xor_sync(~0u, q0, 1); q0 += __shfl_xor_sync(~0u, q0, 2);
    s1 += __shfl_xor_sync(~0u, s1, 1); s1 += __shfl_xor_sync(~0u, s1, 2);
    q1 += __shfl_xor_sync(~0u, q1, 1); q1 += __shfl_xor_sync(~0u, q1, 2);
    if (t == 0) {
        psum[wn * 64 + m0g] = s0;  psq[wn * 64 + m0g] = q0;
        psum[wn * 64 + m0g8] = s1; psq[wn * 64 + m0g8] = q1;
    }
    __syncthreads();
    float ts0 = psum[m0g] + psum[64 + m0g],  tq0 = psq[m0g] + psq[64 + m0g];
    float ts1 = psum[m0g8] + psum[64 + m0g8], tq1 = psq[m0g8] + psq[64 + m0g8];
    mu0 = ts0 * (1.f / 256.f); rs0 = rsqrtf(tq0 * (1.f / 256.f) - mu0 * mu0 + EPS);
    mu1 = ts1 * (1.f / 256.f); rs1 = rsqrtf(tq1 * (1.f / 256.f) - mu1 * mu1 + EPS);
}

__device__ __forceinline__ void norm_split(float (&c)[16][4], const float* gv, const float* bv,
                                           float mu0, float rs0, float mu1, float rs1,
                                           uint2* ap, int wn, int t, int m0g, int m0g8) {
#pragma unroll
    for (int nt = 0; nt < 16; nt++) {
        int cg = wn * 128 + nt * 8 + t * 2;
        float2 gg = *(const float2*)(gv + cg);
        float2 bb = *(const float2*)(bv + cg);
        float v0 = (c[nt][0] - mu0) * rs0 * gg.x + bb.x;
        float v1 = (c[nt][1] - mu0) * rs0 * gg.y + bb.y;
        float v2 = (c[nt][2] - mu1) * rs1 * gg.x + bb.x;
        float v3 = (c[nt][3] - mu1) * rs1 * gg.y + bb.y;
        uint32_t h01, l01, h23, l23;
        split2(v0, v1, h01, l01);
        split2(v2, v3, h23, l23);
        int k2 = (wn * 16 + nt) * 4 + t;
        ap[k2 * 68 + m0g]  = make_uint2(h01, l01);
        ap[k2 * 68 + m0g8] = make_uint2(h23, l23);
    }
}

__device__ __forceinline__ void gelu_split(float (&c)[16][4], const float* bv,
                                           uint2* ap, int wn, int t, int m0g, int m0g8) {
    __syncthreads();   // all warps out of previous GEMM before Apack overwrite
#pragma unroll
    for (int nt = 0; nt < 16; nt++) {
        int cg = wn * 128 + nt * 8 + t * 2;
        float2 bb = *(const float2*)(bv + cg);
        float v0 = gelu(c[nt][0] + bb.x);
        float v1 = gelu(c[nt][1] + bb.y);
        float v2 = gelu(c[nt][2] + bb.x);
        float v3 = gelu(c[nt][3] + bb.y);
        uint32_t h01, l01, h23, l23;
        split2(v0, v1, h01, l01);
        split2(v2, v3, h23, l23);
        int k2 = (wn * 16 + nt) * 4 + t;
        ap[k2 * 68 + m0g]  = make_uint2(h01, l01);
        ap[k2 * 68 + m0g8] = make_uint2(h23, l23);
    }
}

__global__ void __launch_bounds__(NTHR, 2)
stab_hmma(const float* __restrict__ meas, const float* __restrict__ event,
          const float* __restrict__ leak, const float* __restrict__ event_leak,
          const int* __restrict__ stab_ids, const int* __restrict__ cycle_ids,
          const float* __restrict__ w_meas, const float* __restrict__ b_meas,
          const float* __restrict__ w_event, const float* __restrict__ b_event,
          const float* __restrict__ w_leak, const float* __restrict__ b_leak,
          const float* __restrict__ w_el, const float* __restrict__ b_el,
          const float* __restrict__ stab_table, const float* __restrict__ cycle_table,
          const float* __restrict__ g1, const float* __restrict__ be1,
          const float* __restrict__ b11, const float* __restrict__ b12,
          const float* __restrict__ g2, const float* __restrict__ be2,
          const float* __restrict__ b21, const float* __restrict__ b22,
          float* __restrict__ out) {
    extern __shared__ char smem[];
    const uint32_t sb = s2u(smem);
    float*  prm  = (float*)(smem + PRM_OFF);
    float*  psum = (float*)(smem + PS_OFF);
    float*  psq  = (float*)(smem + PSQ_OFF);
    uint2*  ap   = (uint2*)(smem + AP_OFF);
    float*  apf  = (float*)(smem + AP_OFF);   // embed-param staging (before ap is used)

    const int tid = threadIdx.x, w = tid >> 5, lane = tid & 31;
    const int wm = w & 3, wn = w >> 2, t = lane & 3, g = lane >> 2;
    const int m0g = wm * 16 + g, m0g8 = m0g + 8;
    const int base = blockIdx.x * 64;
    const int r0 = base + m0g, r1 = base + m0g8;
    float* xrow0 = out + (size_t)r0 * 256;    // residual x lives in out (thread-private cells)
    float* xrow1 = out + (size_t)r1 * 256;

    {   // permanent params (8KB) + embed staging in ap region (5KB)
        const float* P[8] = {g1, be1, b11, b12, g2, be2, b21, b22};
        for (int i = tid; i < 8 * 256; i += NTHR) prm[i] = P[i >> 8][i & 255];
        const float* Q[4] = {w_meas, w_event, w_leak, w_el};
        for (int i = tid; i < 4 * 256; i += NTHR) apf[256 + i] = Q[i >> 8][i & 255];
        for (int i = tid; i < 256; i += NTHR)
            apf[i] = b_meas[i] + b_event[i] + b_leak[i] + b_el[i];
    }
    __syncthreads();

    float c[16][4];

    // ---- embed (values land directly in C/A-fragment layout); x -> out ----
    {
        float me0 = meas[r0], me1 = meas[r1];
        float ev0 = event[r0], ev1 = event[r1];
        float lk0 = leak[r0], lk1 = leak[r1];
        float el0 = event_leak[r0], el1 = event_leak[r1];
        const float* st0 = stab_table + (size_t)stab_ids[r0] * 256;
        const float* st1 = stab_table + (size_t)stab_ids[r1] * 256;
        const float* cy0 = cycle_table + (size_t)cycle_ids[r0] * 256;
        const float* cy1 = cycle_table + (size_t)cycle_ids[r1] * 256;
#pragma unroll
        for (int nt = 0; nt < 16; nt++) {
            int cg = wn * 128 + nt * 8 + t * 2;
            float2 bc  = *(const float2*)(apf + 0 * 256 + cg);
            float2 wmv = *(const float2*)(apf + 1 * 256 + cg);
            float2 wev = *(const float2*)(apf + 2 * 256 + cg);
            float2 wlv = *(const float2*)(apf + 3 * 256 + cg);
            float2 wzv = *(const float2*)(apf + 4 * 256 + cg);
            float2 s0 = *(const float2*)(st0 + cg), s1 = *(const float2*)(st1 + cg);
            float2 q0 = *(const float2*)(cy0 + cg), q1 = *(const float2*)(cy1 + cg);
            c[nt][0] = bc.x + me0 * wmv.x + ev0 * wev.x + lk0 * wlv.x + el0 * wzv.x + s0.x + q0.x;
            c[nt][1] = bc.y + me0 * wmv.y + ev0 * wev.y + lk0 * wlv.y + el0 * wzv.y + s0.y + q0.y;
            c[nt][2] = bc.x + me1 * wmv.x + ev1 * wev.x + lk1 * wlv.x + el1 * wzv.x + s1.x + q1.x;
            c[nt][3] = bc.y + me1 * wmv.y + ev1 * wev.y + lk1 * wlv.y + el1 * wzv.y + s1.y + q1.y;
            *(float2*)(xrow0 + cg) = make_float2(c[nt][0], c[nt][1]);
            *(float2*)(xrow1 + cg) = make_float2(c[nt][2], c[nt][3]);
        }
    }

    // prefetch GEMM1 chunk0 under the LN1 epilogue
    prefetch_c0(sb, &g_wpack[0][0][0], tid);

    float mu0, rs0, mu1, rs1;
    ln_stats(c, psum, psq, wn, m0g, m0g8, t, mu0, rs0, mu1, rs1);   // syncthreads inside
    norm_split(c, prm + 0 * 256, prm + 1 * 256, mu0, rs0, mu1, rs1, ap, wn, t, m0g, m0g8);

    // GEMM1 ; GELU(+b11)
    gemm256(smem, sb, &g_wpack[0][0][0], c, tid, wn, m0g, m0g8, t);
    prefetch_c0(sb, &g_wpack[1][0][0], tid);
    gelu_split(c, prm + 2 * 256, ap, wn, t, m0g, m0g8);

    // GEMM2 ; x += D + b12 ; LN2
    gemm256(smem, sb, &g_wpack[1][0][0], c, tid, wn, m0g, m0g8, t);
    prefetch_c0(sb, &g_wpack[2][0][0], tid);
#pragma unroll
    for (int nt = 0; nt < 16; nt++) {
        int cg = wn * 128 + nt * 8 + t * 2;
        float2 bb = *(const float2*)(prm + 3 * 256 + cg);
        float2 x0 = *(const float2*)(xrow0 + cg);
        float2 x1 = *(const float2*)(xrow1 + cg);
        c[nt][0] = x0.x + c[nt][0] + bb.x;
        c[nt][1] = x0.y + c[nt][1] + bb.y;
        c[nt][2] = x1.x + c[nt][2] + bb.x;
        c[nt][3] = x1.y + c[nt][3] + bb.y;
        *(float2*)(xrow0 + cg) = make_float2(c[nt][0], c[nt][1]);
        *(float2*)(xrow1 + cg) = make_float2(c[nt][2], c[nt][3]);
    }
    ln_stats(c, psum, psq, wn, m0g, m0g8, t, mu0, rs0, mu1, rs1);
    norm_split(c, prm + 4 * 256, prm + 5 * 256, mu0, rs0, mu1, rs1, ap, wn, t, m0g, m0g8);

    // GEMM3 ; GELU(+b21)
    gemm256(smem, sb, &g_wpack[2][0][0], c, tid, wn, m0g, m0g8, t);
    prefetch_c0(sb, &g_wpack[3][0][0], tid);
    gelu_split(c, prm + 6 * 256, ap, wn, t, m0g, m0g8);

    // GEMM4 ; out = x + D + b22   (x read from out, final overwrites in place)
    gemm256(smem, sb, &g_wpack[3][0][0], c, tid, wn, m0g, m0g8, t);
#pragma unroll
    for (int nt = 0; nt < 16; nt++) {
        int cg = wn * 128 + nt * 8 + t * 2;
        float2 bb = *(const float2*)(prm + 7 * 256 + cg);
        float2 x0 = *(const float2*)(xrow0 + cg);
        float2 x1 = *(const float2*)(xrow1 + cg);
        *(float2*)(xrow0 + cg) =
            make_float2(x0.x + c[nt][0] + bb.x, x0.y + c[nt][1] + bb.y);
        *(float2*)(xrow1 + cg) =
            make_float2(x1.x + c[nt][2] + bb.x, x1.y + c[nt][3] + bb.y);
    }
}

extern "C" void kernel_launch(void* const* d_in, const int* in_sizes, int n_in,
                              void* d_out, int out_size) {
    const float* meas       = (const float*)d_in[0];
    const float* event      = (const float*)d_in[1];
    const float* leak       = (const float*)d_in[2];
    const float* event_leak = (const float*)d_in[3];
    const int*   stab_ids   = (const int*)d_in[4];
    const int*   cycle_ids  = (const int*)d_in[5];
    const float* w_meas  = (const float*)d_in[6];
    const float* b_meas  = (const float*)d_in[7];
    const float* w_event = (const float*)d_in[8];
    const float* b_event = (const float*)d_in[9];
    const float* w_leak  = (const float*)d_in[10];
    const float* b_leak  = (const float*)d_in[11];
    const float* w_el    = (const float*)d_in[12];
    const float* b_el    = (const float*)d_in[13];
    const float* stab_table  = (const float*)d_in[14];
    const float* cycle_table = (const float*)d_in[15];
    const float* g1  = (const float*)d_in[16];
    const float* be1 = (const float*)d_in[17];
    const float* W11 = (const float*)d_in[18];
    const float* b11 = (const float*)d_in[19];
    const float* W12 = (const float*)d_in[20];
    const float* b12 = (const float*)d_in[21];
    const float* g2  = (const float*)d_in[22];
    const float* be2 = (const float*)d_in[23];
    const float* W21 = (const float*)d_in[24];
    const float* b21 = (const float*)d_in[25];
    const float* W22 = (const float*)d_in[26];
    const float* b22 = (const float*)d_in[27];

    const int n_tokens = in_sizes[0];
    const int nblocks  = n_tokens / 64;    // 4096

    prep_w<<<32, 256>>>(W11, W12, W21, W22);

    cudaFuncSetAttribute(stab_hmma,
                         cudaFuncAttributeMaxDynamicSharedMemorySize, SMEM_TOTAL);
    stab_hmma<<<nblocks, NTHR, SMEM_TOTAL>>>(
        meas, event, leak, event_leak, stab_ids, cycle_ids,
        w_meas, b_meas, w_event, b_event, w_leak, b_leak, w_el, b_el,
        stab_table, cycle_table,
        g1, be1, b11, b12, g2, be2, b21, b22,
        (float*)d_out);
}

// round 12
// speedup vs baseline: 1.6037x; 1.1172x over previous
#include <cuda_runtime.h>
#include <cuda_fp16.h>
#include <math.h>
#include <stdint.h>

#define EPS   1e-5f
#define NTHR  256

// ---- SMEM layout (bytes) ----
#define AP_OFF   0                          // Apack hi plane 32KB (embed params staged here first)
#define APL_PL   32768                      // lo plane offset from AP_OFF
#define WB0_OFF  65536                      // 16KB chunk buf
#define WB1_OFF  81920                      // 16KB chunk buf
#define PRM_OFF  98304                      // 8 vec * 1KB
#define PS_OFF   106496                     // 512B
#define PSQ_OFF  107008                     // 512B
#define SMEM_TOTAL 107520                   // 105KB -> 2 CTAs/SM

// prepped fp16 weights: [gemm][chunk 8][4096 u32]; chunk = 2 kt (16KB)
__device__ __align__(16) uint32_t g_wpack[4][8][4096];

__device__ __forceinline__ uint32_t s2u(const void* p) {
    uint32_t a;
    asm("{ .reg .u64 t; cvta.to.shared.u64 t, %1; cvt.u32.u64 %0, t; }" : "=r"(a) : "l"(p));
    return a;
}

__device__ __forceinline__ void hmma(float* c, const uint32_t* a, uint32_t b0, uint32_t b1) {
    asm volatile("mma.sync.aligned.m16n8k16.row.col.f32.f16.f16.f32 "
        "{%0,%1,%2,%3}, {%4,%5,%6,%7}, {%8,%9}, {%0,%1,%2,%3};"
        : "+f"(c[0]), "+f"(c[1]), "+f"(c[2]), "+f"(c[3])
        : "r"(a[0]), "r"(a[1]), "r"(a[2]), "r"(a[3]), "r"(b0), "r"(b1));
}

__device__ __forceinline__ void cp16(uint32_t dst, const void* src) {
    uint64_t gp = __cvta_generic_to_global(src);
    asm volatile("cp.async.cg.shared.global [%0], [%1], 16;" :: "r"(dst), "l"(gp));
}
#define CP_COMMIT() asm volatile("cp.async.commit_group;" ::: "memory")
#define CP_WAIT0()  asm volatile("cp.async.wait_group 0;" ::: "memory")

// 2-term fp16 split of activations
__device__ __forceinline__ void split2(float v0, float v1, uint32_t& hi, uint32_t& lo) {
    __half2 h = __floats2half2_rn(v0, v1);
    float r0 = v0 - __half2float(__low2half(h));
    float r1 = v1 - __half2float(__high2half(h));
    __half2 l = __floats2half2_rn(r0, r1);
    hi = *reinterpret_cast<uint32_t*>(&h);
    lo = *reinterpret_cast<uint32_t*>(&l);
}

__device__ __forceinline__ float gelu(float x) {
    return 0.5f * x * (1.0f + erff(x * 0.70710678118654752f));
}

// ---- prep: pack W (fp32 [k][n]) -> fragment-ready single-fp16 chunks ----
__global__ void prep_w(const float* __restrict__ W11, const float* __restrict__ W12,
                       const float* __restrict__ W21, const float* __restrict__ W22) {
    const float* Ws[4] = {W11, W12, W21, W22};
    int gi = blockIdx.x >> 3, cc = blockIdx.x & 7;
    const float* W = Ws[gi];
    for (int i = threadIdx.x; i < 4096; i += blockDim.x) {
        int kt_local = i >> 11;
        int j = i & 2047;
        int ntp = j >> 7;
        int lane = (j >> 2) & 31;
        int comp = j & 3;
        int nt = ntp * 2 + (comp >> 1);
        int which = comp & 1;
        int t = lane & 3, gg = lane >> 2;
        int n = nt * 8 + gg;
        int k = (cc * 2 + kt_local) * 16 + t * 2 + which * 8;
        __half2 r = __floats2half2_rn(W[k * 256 + n], W[(k + 1) * 256 + n]);
        g_wpack[gi][cc][i] = *reinterpret_cast<uint32_t*>(&r);
    }
}

// chunk-0 prefetch (into WB0) — overlaps preceding epilogue
__device__ __forceinline__ void prefetch_c0(uint32_t sb, const uint32_t* wsrc, int tid) {
    uint32_t d = sb + WB0_OFF + tid * 16;
    const char* s = (const char*)wsrc + tid * 16;
#pragma unroll
    for (int i = 0; i < 4; i++) cp16(d + i * 4096, s + i * 4096);
    CP_COMMIT();
}

// ---- one fused 64x256x256 GEMM (2-term fp16); chunk0 already in flight ----
// A fragments read as whole 16B cells: cell(kt,t,wm,g) = {a0,a1,a2,a3}
__device__ __forceinline__ void gemm256(const char* smem, uint32_t sb, const uint32_t* wsrc,
                                        float (&c)[16][4], int tid, int wn,
                                        const char* apbase) {
#pragma unroll
    for (int nt = 0; nt < 16; nt++)
#pragma unroll
        for (int q = 0; q < 4; q++) c[nt][q] = 0.f;

    const uint32_t dst0 = sb + WB0_OFF + tid * 16;
    const uint32_t dst1 = sb + WB1_OFF + tid * 16;
    const char* src = (const char*)wsrc + tid * 16;
    const char* wb0 = smem + WB0_OFF + wn * 4096 + (tid & 31) * 16;
    const char* wb1 = smem + WB1_OFF + wn * 4096 + (tid & 31) * 16;

#pragma unroll
    for (int ch = 0; ch < 8; ch++) {
        CP_WAIT0();
        __syncthreads();
        if (ch + 1 < 8) {
            uint32_t d = ((ch + 1) & 1) ? dst1 : dst0;
            const char* s = src + (ch + 1) * 16384;
#pragma unroll
            for (int i = 0; i < 4; i++) cp16(d + i * 4096, s + i * 4096);
            CP_COMMIT();
        }
        const char* wb = (ch & 1) ? wb1 : wb0;
#pragma unroll
        for (int kl = 0; kl < 2; kl++) {
            const int kt = ch * 2 + kl;
            uint4 ah = *(const uint4*)(apbase + kt * 2048);
            uint4 al = *(const uint4*)(apbase + kt * 2048 + APL_PL);
            uint32_t ahi[4] = {ah.x, ah.y, ah.z, ah.w};
            uint32_t alo[4] = {al.x, al.y, al.z, al.w};
            const char* wbk = wb + kl * 8192;
#pragma unroll
            for (int jj = 0; jj < 8; jj++) {
                uint4 b = *(const uint4*)(wbk + jj * 512);
                hmma(c[jj * 2],     ahi, b.x, b.y);
                hmma(c[jj * 2],     alo, b.x, b.y);
                hmma(c[jj * 2 + 1], ahi, b.z, b.w);
                hmma(c[jj * 2 + 1], alo, b.z, b.w);
            }
        }
    }
}

__device__ __forceinline__ void ln_stats(float (&c)[16][4], float* psum, float* psq,
                                         int wn, int m0g, int m0g8, int t,
                                         float& mu0, float& rs0, float& mu1, float& rs1) {
    float s0 = 0, q0 = 0, s1 = 0, q1 = 0;
#pragma unroll
    for (int nt = 0; nt < 16; nt++) {
        s0 += c[nt][0] + c[nt][1]; q0 += c[nt][0] * c[nt][0] + c[nt][1] * c[nt][1];
        s1 += c[nt][2] + c[nt][3]; q1 += c[nt][2] * c[nt][2] + c[nt][3] * c[nt][3];
    }
    s0 += __shfl_xor_sync(~0u, s0, 1); s0 += __shfl_xor_sync(~0u, s0, 2);
    q0 += __shfl_xor_sync(~0u, q0, 1); q0 += __shfl_xor_sync(~0u, q0, 2);
    s1 += __shfl_xor_sync(~0u, s1, 1); s1 += __shfl_xor_sync(~0u, s1, 2);
    q1 += __shfl_xor_sync(~0u, q1, 1); q1 += __shfl_xor_sync(~0u, q1, 2);
    if (t == 0) {
        psum[wn * 64 + m0g] = s0;  psq[wn * 64 + m0g] = q0;
        psum[wn * 64 + m0g8] = s1; psq[wn * 64 + m0g8] = q1;
    }
    __syncthreads();
    float ts0 = psum[m0g] + psum[64 + m0g],  tq0 = psq[m0g] + psq[64 + m0g];
    float ts1 = psum[m0g8] + psum[64 + m0g8], tq1 = psq[m0g8] + psq[64 + m0g8];
    mu0 = ts0 * (1.f / 256.f); rs0 = rsqrtf(tq0 * (1.f / 256.f) - mu0 * mu0 + EPS);
    mu1 = ts1 * (1.f / 256.f); rs1 = rsqrtf(tq1 * (1.f / 256.f) - mu1 * mu1 + EPS);
}

// writer: per nt-pair p, one 16B hi cell + one 16B lo cell at apw + p*2048
__device__ __forceinline__ void norm_split(float (&c)[16][4], const float* gv, const float* bv,
                                           float mu0, float rs0, float mu1, float rs1,
                                           char* apw, int wn, int t) {
#pragma unroll
    for (int p = 0; p < 8; p++) {
        uint32_t hi[4], lo[4];
#pragma unroll
        for (int e = 0; e < 2; e++) {
            int nt = 2 * p + e;
            int cg = wn * 128 + nt * 8 + t * 2;
            float2 gg = *(const float2*)(gv + cg);
            float2 bb = *(const float2*)(bv + cg);
            float v0 = (c[nt][0] - mu0) * rs0 * gg.x + bb.x;
            float v1 = (c[nt][1] - mu0) * rs0 * gg.y + bb.y;
            float v2 = (c[nt][2] - mu1) * rs1 * gg.x + bb.x;
            float v3 = (c[nt][3] - mu1) * rs1 * gg.y + bb.y;
            split2(v0, v1, hi[e * 2], lo[e * 2]);
            split2(v2, v3, hi[e * 2 + 1], lo[e * 2 + 1]);
        }
        *(uint4*)(apw + p * 2048)          = make_uint4(hi[0], hi[1], hi[2], hi[3]);
        *(uint4*)(apw + p * 2048 + APL_PL) = make_uint4(lo[0], lo[1], lo[2], lo[3]);
    }
}

__device__ __forceinline__ void gelu_split(float (&c)[16][4], const float* bv,
                                           char* apw, int wn, int t) {
    __syncthreads();   // all warps out of previous GEMM before Apack overwrite
#pragma unroll
    for (int p = 0; p < 8; p++) {
        uint32_t hi[4], lo[4];
#pragma unroll
        for (int e = 0; e < 2; e++) {
            int nt = 2 * p + e;
            int cg = wn * 128 + nt * 8 + t * 2;
            float2 bb = *(const float2*)(bv + cg);
            float v0 = gelu(c[nt][0] + bb.x);
            float v1 = gelu(c[nt][1] + bb.y);
            float v2 = gelu(c[nt][2] + bb.x);
            float v3 = gelu(c[nt][3] + bb.y);
            split2(v0, v1, hi[e * 2], lo[e * 2]);
            split2(v2, v3, hi[e * 2 + 1], lo[e * 2 + 1]);
        }
        *(uint4*)(apw + p * 2048)          = make_uint4(hi[0], hi[1], hi[2], hi[3]);
        *(uint4*)(apw + p * 2048 + APL_PL) = make_uint4(lo[0], lo[1], lo[2], lo[3]);
    }
}

__global__ void __launch_bounds__(NTHR, 2)
stab_hmma(const float* __restrict__ meas, const float* __restrict__ event,
          const float* __restrict__ leak, const float* __restrict__ event_leak,
          const int* __restrict__ stab_ids, const int* __restrict__ cycle_ids,
          const float* __restrict__ w_meas, const float* __restrict__ b_meas,
          const float* __restrict__ w_event, const float* __restrict__ b_event,
          const float* __restrict__ w_leak, const float* __restrict__ b_leak,
          const float* __restrict__ w_el, const float* __restrict__ b_el,
          const float* __restrict__ stab_table, const float* __restrict__ cycle_table,
          const float* __restrict__ g1, const float* __restrict__ be1,
          const float* __restrict__ b11, const float* __restrict__ b12,
          const float* __restrict__ g2, const float* __restrict__ be2,
          const float* __restrict__ b21, const float* __restrict__ b22,
          float* __restrict__ out) {
    extern __shared__ char smem[];
    const uint32_t sb = s2u(smem);
    float*  prm  = (float*)(smem + PRM_OFF);
    float*  psum = (float*)(smem + PS_OFF);
    float*  psq  = (float*)(smem + PSQ_OFF);
    float*  apf  = (float*)(smem + AP_OFF);   // embed-param staging (before Apack is used)

    const int tid = threadIdx.x, w = tid >> 5, lane = tid & 31;
    const int wm = w & 3, wn = w >> 2, t = lane & 3, g = lane >> 2;
    const int m0g = wm * 16 + g, m0g8 = m0g + 8;
    const int base = blockIdx.x * 64;
    const int r0 = base + m0g, r1 = base + m0g8;
    float* xrow0 = out + (size_t)r0 * 256;    // residual x lives in out
    float* xrow1 = out + (size_t)r1 * 256;

    // A cell addresses: reader base (kt=0) and writer base (kt = wn*8)
    const char* apr = smem + AP_OFF + (t * 32 + wm * 8 + g) * 16;
    char*       apw = smem + AP_OFF + ((wn * 32 + t) * 32 + wm * 8 + g) * 16;

    {   // permanent params (8KB) + embed staging in Apack region (5KB)
        const float* P[8] = {g1, be1, b11, b12, g2, be2, b21, b22};
        for (int i = tid; i < 8 * 256; i += NTHR) prm[i] = P[i >> 8][i & 255];
        const float* Q[4] = {w_meas, w_event, w_leak, w_el};
        for (int i = tid; i < 4 * 256; i += NTHR) apf[256 + i] = Q[i >> 8][i & 255];
        for (int i = tid; i < 256; i += NTHR)
            apf[i] = b_meas[i] + b_event[i] + b_leak[i] + b_el[i];
    }
    __syncthreads();

    float c[16][4];

    // ---- embed (values land directly in C/A-fragment layout); x -> out ----
    {
        float me0 = meas[r0], me1 = meas[r1];
        float ev0 = event[r0], ev1 = event[r1];
        float lk0 = leak[r0], lk1 = leak[r1];
        float el0 = event_leak[r0], el1 = event_leak[r1];
        const float* st0 = stab_table + (size_t)stab_ids[r0] * 256;
        const float* st1 = stab_table + (size_t)stab_ids[r1] * 256;
        const float* cy0 = cycle_table + (size_t)cycle_ids[r0] * 256;
        const float* cy1 = cycle_table + (size_t)cycle_ids[r1] * 256;
#pragma unroll
        for (int nt = 0; nt < 16; nt++) {
            int cg = wn * 128 + nt * 8 + t * 2;
            float2 bc  = *(const float2*)(apf + 0 * 256 + cg);
            float2 wmv = *(const float2*)(apf + 1 * 256 + cg);
            float2 wev = *(const float2*)(apf + 2 * 256 + cg);
            float2 wlv = *(const float2*)(apf + 3 * 256 + cg);
            float2 wzv = *(const float2*)(apf + 4 * 256 + cg);
            float2 s0 = *(const float2*)(st0 + cg), s1 = *(const float2*)(st1 + cg);
            float2 q0 = *(const float2*)(cy0 + cg), q1 = *(const float2*)(cy1 + cg);
            c[nt][0] = bc.x + me0 * wmv.x + ev0 * wev.x + lk0 * wlv.x + el0 * wzv.x + s0.x + q0.x;
            c[nt][1] = bc.y + me0 * wmv.y + ev0 * wev.y + lk0 * wlv.y + el0 * wzv.y + s0.y + q0.y;
            c[nt][2] = bc.x + me1 * wmv.x + ev1 * wev.x + lk1 * wlv.x + el1 * wzv.x + s1.x + q1.x;
            c[nt][3] = bc.y + me1 * wmv.y + ev1 * wev.y + lk1 * wlv.y + el1 * wzv.y + s1.y + q1.y;
            *(float2*)(xrow0 + cg) = make_float2(c[nt][0], c[nt][1]);
            *(float2*)(xrow1 + cg) = make_float2(c[nt][2], c[nt][3]);
        }
    }

    // prefetch GEMM1 chunk0 under the LN1 epilogue
    prefetch_c0(sb, &g_wpack[0][0][0], tid);

    float mu0, rs0, mu1, rs1;
    ln_stats(c, psum, psq, wn, m0g, m0g8, t, mu0, rs0, mu1, rs1);   // syncthreads inside
    norm_split(c, prm + 0 * 256, prm + 1 * 256, mu0, rs0, mu1, rs1, apw, wn, t);

    // GEMM1 ; GELU(+b11)
    gemm256(smem, sb, &g_wpack[0][0][0], c, tid, wn, apr);
    prefetch_c0(sb, &g_wpack[1][0][0], tid);
    gelu_split(c, prm + 2 * 256, apw, wn, t);

    // GEMM2 ; x += D + b12 ; LN2
    gemm256(smem, sb, &g_wpack[1][0][0], c, tid, wn, apr);
    prefetch_c0(sb, &g_wpack[2][0][0], tid);
#pragma unroll
    for (int nt = 0; nt < 16; nt++) {
        int cg = wn * 128 + nt * 8 + t * 2;
        float2 bb = *(const float2*)(prm + 3 * 256 + cg);
        float2 x0 = *(const float2*)(xrow0 + cg);
        float2 x1 = *(const float2*)(xrow1 + cg);
        c[nt][0] = x0.x + c[nt][0] + bb.x;
        c[nt][1] = x0.y + c[nt][1] + bb.y;
        c[nt][2] = x1.x + c[nt][2] + bb.x;
        c[nt][3] = x1.y + c[nt][3] + bb.y;
        *(float2*)(xrow0 + cg) = make_float2(c[nt][0], c[nt][1]);
        *(float2*)(xrow1 + cg) = make_float2(c[nt][2], c[nt][3]);
    }
    ln_stats(c, psum, psq, wn, m0g, m0g8, t, mu0, rs0, mu1, rs1);
    norm_split(c, prm + 4 * 256, prm + 5 * 256, mu0, rs0, mu1, rs1, apw, wn, t);

    // GEMM3 ; GELU(+b21)
    gemm256(smem, sb, &g_wpack[2][0][0], c, tid, wn, apr);
    prefetch_c0(sb, &g_wpack[3][0][0], tid);
    gelu_split(c, prm + 6 * 256, apw, wn, t);

    // GEMM4 ; out = x + D + b22   (x read from out, final overwrites in place)
    gemm256(smem, sb, &g_wpack[3][0][0], c, tid, wn, apr);
#pragma unroll
    for (int nt = 0; nt < 16; nt++) {
        int cg = wn * 128 + nt * 8 + t * 2;
        float2 bb = *(const float2*)(prm + 7 * 256 + cg);
        float2 x0 = *(const float2*)(xrow0 + cg);
        float2 x1 = *(const float2*)(xrow1 + cg);
        *(float2*)(xrow0 + cg) =
            make_float2(x0.x + c[nt][0] + bb.x, x0.y + c[nt][1] + bb.y);
        *(float2*)(xrow1 + cg) =
            make_float2(x1.x + c[nt][2] + bb.x, x1.y + c[nt][3] + bb.y);
    }
}

extern "C" void kernel_launch(void* const* d_in, const int* in_sizes, int n_in,
                              void* d_out, int out_size) {
    const float* meas       = (const float*)d_in[0];
    const float* event      = (const float*)d_in[1];
    const float* leak       = (const float*)d_in[2];
    const float* event_leak = (const float*)d_in[3];
    const int*   stab_ids   = (const int*)d_in[4];
    const int*   cycle_ids  = (const int*)d_in[5];
    const float* w_meas  = (const float*)d_in[6];
    const float* b_meas  = (const float*)d_in[7];
    const float* w_event = (const float*)d_in[8];
    const float* b_event = (const float*)d_in[9];
    const float* w_leak  = (const float*)d_in[10];
    const float* b_leak  = (const float*)d_in[11];
    const float* w_el    = (const float*)d_in[12];
    const float* b_el    = (const float*)d_in[13];
    const float* stab_table  = (const float*)d_in[14];
    const float* cycle_table = (const float*)d_in[15];
    const float* g1  = (const float*)d_in[16];
    const float* be1 = (const float*)d_in[17];
    const float* W11 = (const float*)d_in[18];
    const float* b11 = (const float*)d_in[19];
    const float* W12 = (const float*)d_in[20];
    const float* b12 = (const float*)d_in[21];
    const float* g2  = (const float*)d_in[22];
    const float* be2 = (const float*)d_in[23];
    const float* W21 = (const float*)d_in[24];
    const float* b21 = (const float*)d_in[25];
    const float* W22 = (const float*)d_in[26];
    const float* b22 = (const float*)d_in[27];

    const int n_tokens = in_sizes[0];
    const int nblocks  = n_tokens / 64;    // 4096

    prep_w<<<32, 256>>>(W11, W12, W21, W22);

    cudaFuncSetAttribute(stab_hmma,
                         cudaFuncAttributeMaxDynamicSharedMemorySize, SMEM_TOTAL);
    stab_hmma<<<nblocks, NTHR, SMEM_TOTAL>>>(
        meas, event, leak, event_leak, stab_ids, cycle_ids,
        w_meas, b_meas, w_event, b_event, w_leak, b_leak, w_el, b_el,
        stab_table, cycle_table,
        g1, be1, b11, b12, g2, be2, b21, b22,
        (float*)d_out);
}